// round 8
// baseline (speedup 1.0000x reference)
#include <cuda_runtime.h>
#include <cuda_bf16.h>
#include <cstdint>
#include <math.h>

#define BB 64
#define TT 256
#define HH 256
#define DD 128

// ---- scratch (device globals: no allocation allowed) ----
__device__ float g_xproj[(size_t)BB * TT * 768];   // [b*T+t][768]
__device__ float g_enc[(size_t)BB * TT * HH];      // [b*T+t][256]
__device__ float g_anchor[BB * 2];

// output layout (floats), concatenated in reference return order:
// mean_z [64,256,8] | chol_z [8,64,256,256] | mean_x [16384,8] | cov_x [16384,8,8]
#define OFF_MZ   0ull
#define OFF_CHOL 131072ull
#define OFF_MX   33685504ull
#define OFF_CX   33816576ull

// GRU dynamic smem layout (floats):
//   [0, 1024)            h_s   [phase][batch][HH]   (2*2*256)
//   [1024, 4160)         red   64 rows * 49 stride
//   [4160, 20800)        Wn    64 rows * 260 stride (gate-n weights)
#define GRU_HS_OFF   0
#define GRU_RED_OFF  1024
#define GRU_WN_OFF   4160
#define GRU_WN_STR   260
#define GRU_SMEM_FLOATS (GRU_WN_OFF + 64 * GRU_WN_STR)   // 20800
#define GRU_SMEM_BYTES  (GRU_SMEM_FLOATS * 4)            // 83200

// ============================================================
// 1) x_proj = y @ W_ih^T + b_ih : [16384,128] x [128,768]
// ============================================================
__global__ void __launch_bounds__(256) xproj_kernel(const float* __restrict__ y,
                                                    const float* __restrict__ Wih,
                                                    const float* __restrict__ bih)
{
    __shared__ float As[64][68];   // [k][m]
    __shared__ float Bs[64][68];   // [k][n]
    const int tid = threadIdx.x;
    const int tx = tid & 15;       // n/4
    const int ty = tid >> 4;       // m/4
    const int m0 = blockIdx.x * 64;
    const int n0 = blockIdx.y * 64;

    float acc[4][4];
#pragma unroll
    for (int i = 0; i < 4; i++)
#pragma unroll
        for (int j = 0; j < 4; j++) acc[i][j] = 0.f;

    for (int kp = 0; kp < 128; kp += 64) {
        __syncthreads();
#pragma unroll
        for (int l = 0; l < 4; l++) {
            int lin = tid + l * 256;
            int row = lin >> 4;
            int kq  = lin & 15;
            float4 va = *(const float4*)(y   + (size_t)(m0 + row) * DD + kp + kq * 4);
            float4 vb = *(const float4*)(Wih + (size_t)(n0 + row) * DD + kp + kq * 4);
            As[kq * 4 + 0][row] = va.x; As[kq * 4 + 1][row] = va.y;
            As[kq * 4 + 2][row] = va.z; As[kq * 4 + 3][row] = va.w;
            Bs[kq * 4 + 0][row] = vb.x; Bs[kq * 4 + 1][row] = vb.y;
            Bs[kq * 4 + 2][row] = vb.z; Bs[kq * 4 + 3][row] = vb.w;
        }
        __syncthreads();
#pragma unroll
        for (int k = 0; k < 64; k++) {
            float4 av = *(const float4*)&As[k][ty * 4];
            float4 bv = *(const float4*)&Bs[k][tx * 4];
            float a[4] = {av.x, av.y, av.z, av.w};
            float b[4] = {bv.x, bv.y, bv.z, bv.w};
#pragma unroll
            for (int i = 0; i < 4; i++)
#pragma unroll
                for (int j = 0; j < 4; j++) acc[i][j] = fmaf(a[i], b[j], acc[i][j]);
        }
    }
#pragma unroll
    for (int j = 0; j < 4; j++) {
        float b = bih[n0 + tx * 4 + j];
#pragma unroll
        for (int i = 0; i < 4; i++) acc[i][j] += b;
    }
#pragma unroll
    for (int i = 0; i < 4; i++) {
        float* o = g_xproj + (size_t)(m0 + ty * 4 + i) * 768 + n0 + tx * 4;
        *(float4*)o = make_float4(acc[i][0], acc[i][1], acc[i][2], acc[i][3]);
    }
}

// ============================================================
// 2) GRU: 32 clusters x 4 CTAs, 2 batches/cluster.
//    CTA rank m owns hidden units [m*64, m*64+64) for all 3 gates.
//    Gates r,z weights in REGISTERS (64/thread); gate-n weights in
//    dynamic SMEM. h double-buffered in SMEM, broadcast via
//    st.shared::cluster + barrier.cluster.
// ============================================================
__global__ void __cluster_dims__(4, 1, 1) __launch_bounds__(512, 1)
gru_kernel(const float* __restrict__ Whh, const float* __restrict__ bhh)
{
    extern __shared__ float dsm[];
    float* h_s = dsm + GRU_HS_OFF;     // [(ph*2 + b)*HH + idx]
    float* red = dsm + GRU_RED_OFF;    // [j*49 + slot]
    float* Wn  = dsm + GRU_WN_OFF;     // [j*GRU_WN_STR + k]

    const int tid  = threadIdx.x;
    const int j    = tid & 63;
    const int ks   = tid >> 6;                 // 0..7 (k-slice of 32)
    const int rank = blockIdx.x & 3;
    const int u0   = rank * 64;
    const int bg   = (blockIdx.x >> 2) * 2;    // global batch base

    // register-resident W for gates r,z: rows g*256+u0+j, cols ks*32..+32
    float W[2][32];
#pragma unroll
    for (int g = 0; g < 2; g++) {
        const float4* wp = (const float4*)(Whh + (size_t)(g * HH + u0 + j) * HH + ks * 32);
#pragma unroll
        for (int q = 0; q < 8; q++) {
            float4 v = wp[q];
            W[g][4 * q + 0] = v.x; W[g][4 * q + 1] = v.y;
            W[g][4 * q + 2] = v.z; W[g][4 * q + 3] = v.w;
        }
    }
    // SMEM-resident gate-n weights: Wn[j][k] = Whh[(2H + u0 + j)*H + k]
    {
        const float4* wp = (const float4*)(Whh + (size_t)(2 * HH + u0 + j) * HH + ks * 32);
        float4* dp = (float4*)&Wn[j * GRU_WN_STR + ks * 32];
#pragma unroll
        for (int q = 0; q < 8; q++) dp[q] = wp[q];
    }
    float bh0 = 0.f, bh1 = 0.f, bh2 = 0.f;
    if (tid < 128) {
        int jr = tid & 63;
        bh0 = bhh[u0 + jr];
        bh1 = bhh[HH + u0 + jr];
        bh2 = bhh[2 * HH + u0 + jr];
    }
    for (int i = tid; i < 2 * 2 * HH; i += 512) h_s[i] = 0.f;

    uint32_t hbase;
    asm("{ .reg .u64 t; cvta.to.shared.u64 t, %1; cvt.u32.u64 %0, t; }"
        : "=r"(hbase) : "l"((void*)h_s));

    __syncthreads();
    asm volatile("barrier.cluster.arrive.aligned;" ::: "memory");
    asm volatile("barrier.cluster.wait.aligned;" ::: "memory");

    for (int t = 0; t < TT; t++) {
        const int ph = t & 1;
        float xr = 0.f, xz = 0.f, xn = 0.f;
        if (tid < 128) {
            const int b = tid >> 6, jr = tid & 63;
            const float* xp = g_xproj + ((size_t)(bg + b) * TT + t) * 768 + u0 + jr;
            xr = xp[0]; xz = xp[HH]; xn = xp[2 * HH];
        }
        // partial dots: 3 gates x 2 batches over this thread's 32 k's
        float a00 = 0.f, a01 = 0.f, a10 = 0.f, a11 = 0.f, a20 = 0.f, a21 = 0.f;
        const float4* h0v = (const float4*)&h_s[(ph * 2 + 0) * HH + ks * 32];
        const float4* h1v = (const float4*)&h_s[(ph * 2 + 1) * HH + ks * 32];
        const float4* wnv = (const float4*)&Wn[j * GRU_WN_STR + ks * 32];
#pragma unroll
        for (int q = 0; q < 8; q++) {
            float4 va = h0v[q];
            float4 vb = h1v[q];
            float4 wn = wnv[q];
            float ha[4] = {va.x, va.y, va.z, va.w};
            float hb[4] = {vb.x, vb.y, vb.z, vb.w};
            float wnn[4] = {wn.x, wn.y, wn.z, wn.w};
#pragma unroll
            for (int c = 0; c < 4; c++) {
                float w0 = W[0][4 * q + c], w1 = W[1][4 * q + c], w2 = wnn[c];
                a00 = fmaf(w0, ha[c], a00); a01 = fmaf(w0, hb[c], a01);
                a10 = fmaf(w1, ha[c], a10); a11 = fmaf(w1, hb[c], a11);
                a20 = fmaf(w2, ha[c], a20); a21 = fmaf(w2, hb[c], a21);
            }
        }
        float* rbase = red + j * 49;
        rbase[ks]      = a00; rbase[8 + ks]  = a01;
        rbase[16 + ks] = a10; rbase[24 + ks] = a11;
        rbase[32 + ks] = a20; rbase[40 + ks] = a21;
        __syncthreads();
        if (tid < 128) {
            const int b = tid >> 6, jr = tid & 63;
            const float* rp = red + jr * 49 + b * 8;
            float sr = bh0, sz = bh1, sn = bh2;
#pragma unroll
            for (int k = 0; k < 8; k++) {
                sr += rp[k]; sz += rp[16 + k]; sn += rp[32 + k];
            }
            float r = 1.f / (1.f + expf(-(xr + sr)));
            float z = 1.f / (1.f + expf(-(xz + sz)));
            float n = tanhf(xn + r * sn);
            float hold = h_s[(ph * 2 + b) * HH + u0 + jr];
            float hnew = fmaf(z, hold - n, n);   // (1-z)*n + z*h
            g_enc[((size_t)(bg + b) * TT + t) * HH + u0 + jr] = hnew;
            uint32_t laddr = hbase + (uint32_t)(((((ph ^ 1) * 2 + b) * HH) + u0 + jr) * 4);
#pragma unroll
            for (int p = 0; p < 4; p++) {
                uint32_t raddr;
                asm("mapa.shared::cluster.u32 %0, %1, %2;" : "=r"(raddr) : "r"(laddr), "r"(p));
                asm volatile("st.shared::cluster.f32 [%0], %1;" :: "r"(raddr), "f"(hnew));
            }
        }
        asm volatile("barrier.cluster.arrive.aligned;" ::: "memory");
        asm volatile("barrier.cluster.wait.aligned;" ::: "memory");
    }
}

// ============================================================
// 3) zero-fill chol_z region (134 MB)
// ============================================================
__global__ void zero_kernel(float4* __restrict__ p, int n4)
{
    int i = blockIdx.x * blockDim.x + threadIdx.x;
    int stride = gridDim.x * blockDim.x;
    for (; i < n4; i += stride) p[i] = make_float4(0.f, 0.f, 0.f, 0.f);
}

// ============================================================
// 4) anchor: mean_x at t=0, dims 0..1, per batch (incl. bias)
// ============================================================
__global__ void anchor_kernel(const float* __restrict__ Wmx, const float* __restrict__ bmx)
{
    int tid = threadIdx.x;
    if (tid < 128) {
        int b = tid >> 1, d = tid & 1;
        const float* e = g_enc + (size_t)b * TT * HH;   // t = 0 row
        const float* w = Wmx + d * HH;
        float s = bmx[d];
        for (int k = 0; k < HH; k++) s = fmaf(e[k], w[k], s);
        g_anchor[b * 2 + d] = s;
    }
}

// ============================================================
// 5) heads: enc[16384,256] x W_all^T[256,96] + transforms + scatter
//    r: [0,8)=mean_z [8,16)=mean_x [16,32)=bd_z [32,96)=cov_x
//    threads: 384 = (r 0..95) x (kc 0..3, 64-k chunks), W in regs
// ============================================================
__global__ void __launch_bounds__(384) heads_kernel(
    const float* __restrict__ Wmz, const float* __restrict__ bmz,
    const float* __restrict__ Wmx, const float* __restrict__ bmx,
    const float* __restrict__ Wpz, const float* __restrict__ bpz,
    const float* __restrict__ Wcx, const float* __restrict__ bcx,
    float* __restrict__ out)
{
    __shared__ float encsm[256];
    __shared__ float red[384];

    const int tid = threadIdx.x;
    const int r  = tid % 96;
    const int kc = tid / 96;

    // select weight row + bias for this r
    const float* wrow;
    float bias;
    if (r < 8)       { wrow = Wmz + (size_t)r * HH;        bias = bmz[r]; }
    else if (r < 16) { wrow = Wmx + (size_t)(r - 8) * HH;  bias = bmx[r - 8]; }
    else if (r < 32) { wrow = Wpz + (size_t)(r - 16) * HH; bias = bpz[r - 16]; }
    else             { wrow = Wcx + (size_t)(r - 32) * HH; bias = bcx[r - 32]; }

    float W[64];
    {
        const float4* wp = (const float4*)(wrow + kc * 64);
#pragma unroll
        for (int q = 0; q < 16; q++) {
            float4 v = wp[q];
            W[4 * q + 0] = v.x; W[4 * q + 1] = v.y;
            W[4 * q + 2] = v.z; W[4 * q + 3] = v.w;
        }
    }

    const int row0 = blockIdx.x * 128;
    for (int i = 0; i < 128; i++) {
        const int row = row0 + i;
        __syncthreads();
        if (tid < 64) {
            *(float4*)&encsm[tid * 4] = *(const float4*)(g_enc + (size_t)row * HH + tid * 4);
        }
        __syncthreads();
        float s = 0.f;
        const float4* ev = (const float4*)&encsm[kc * 64];
#pragma unroll
        for (int q = 0; q < 16; q++) {
            float4 v = ev[q];
            s = fmaf(W[4 * q + 0], v.x, s);
            s = fmaf(W[4 * q + 1], v.y, s);
            s = fmaf(W[4 * q + 2], v.z, s);
            s = fmaf(W[4 * q + 3], v.w, s);
        }
        red[kc * 96 + r] = s;
        __syncthreads();
        if (tid < 96) {
            float v = red[tid] + red[96 + tid] + red[192 + tid] + red[288 + tid] + bias;
            const int b = row >> 8, t = row & 255;
            if (tid < 8) {
                out[OFF_MZ + (size_t)row * 8 + tid] = v;
            } else if (tid < 16) {
                int d = tid - 8;
                float a = (d < 2) ? g_anchor[b * 2 + d] : 0.f;
                out[OFF_MX + (size_t)row * 8 + d] = v - a;
            } else if (tid < 32) {
                int d = tid - 16;
                if (d < 8) {
                    // diag: softplus
                    float sp = (v > 20.f) ? v : log1pf(expf(v));
                    out[OFF_CHOL + (((size_t)d * BB + b) * TT + t) * TT + t] = sp;
                } else {
                    int dz = d - 8;
                    if (t < TT - 1)
                        out[OFF_CHOL + (((size_t)dz * BB + b) * TT + t) * TT + (t + 1)] = v;
                }
            } else {
                out[OFF_CX + (size_t)row * 64 + (tid - 32)] = v;
            }
        }
    }
}

extern "C" void kernel_launch(void* const* d_in, const int* in_sizes, int n_in,
                              void* d_out, int out_size)
{
    const float* y    = (const float*)d_in[0];
    const float* Wih  = (const float*)d_in[1];
    const float* Whh  = (const float*)d_in[2];
    const float* bih  = (const float*)d_in[3];
    const float* bhh  = (const float*)d_in[4];
    const float* Wmz  = (const float*)d_in[5];
    const float* bmz  = (const float*)d_in[6];
    const float* Wmx  = (const float*)d_in[7];
    const float* bmx  = (const float*)d_in[8];
    const float* Wpz  = (const float*)d_in[9];
    const float* bpz  = (const float*)d_in[10];
    const float* Wcx  = (const float*)d_in[11];
    const float* bcx  = (const float*)d_in[12];
    float* out = (float*)d_out;

    // allow >48KB dynamic smem for the GRU (host attribute, idempotent,
    // not a stream op -> graph-capture safe)
    cudaFuncSetAttribute(gru_kernel, cudaFuncAttributeMaxDynamicSharedMemorySize,
                         GRU_SMEM_BYTES);

    // zero the chol region (rest is fully overwritten by heads)
    zero_kernel<<<4096, 256>>>((float4*)(out + OFF_CHOL), (int)(33554432 / 4));

    dim3 gx(256, 12);
    xproj_kernel<<<gx, 256>>>(y, Wih, bih);

    gru_kernel<<<128, 512, GRU_SMEM_BYTES>>>(Whh, bhh);

    anchor_kernel<<<1, 128>>>(Wmx, bmx);

    heads_kernel<<<128, 384>>>(Wmz, bmz, Wmx, bmx, Wpz, bpz, Wcx, bcx, out);
}